// round 8
// baseline (speedup 1.0000x reference)
#include <cuda_runtime.h>
#include <math.h>

#define D 256
#define O 10
#define NS 64
#define R 640   // NS*O

// ---------------- scratch ----------------
__device__ float d_W2P[D * D];     // float4 at (k4*D + t) holds W2[t][4k4..4k4+3]
__device__ float d_H1[2 * NS * D];
__device__ float d_H2[2 * NS * D];
__device__ float d_G1[2 * R * D];
__device__ float d_G2[2 * R * D];
__device__ float d_C[3][NS * NS];

// ======== kA: layer-1 GEMM  H1 = tanh(X @ W1 + b1)  + W2 pack (blocks 0..63) =====
// GEMM blocks 64..71: 64(samples) x 64(units) tile, K=256 in 8 double-buffered
// 32-deep stages. A = x1/x2 rows (transposed into smem), B = W1 (k-major, direct).
__global__ __launch_bounds__(256) void kA_l1(
    const float* __restrict__ x1, const float* __restrict__ x2,
    const float* __restrict__ W1, const float* __restrict__ b1,
    const float* __restrict__ W2)
{
    const int b = blockIdx.x, tid = threadIdx.x;

    if (b < 64) {   // pack W2 for kC: W2P[(k4*D + t)*4 + c] = W2[t][k4*4+c]
        int gid = b * 256 + tid;
        int k4 = gid & 63, tw = gid >> 6;
        float4 v = *(const float4*)&W2[tw * D + k4 * 4];
        *(float4*)&d_W2P[(k4 * D + tw) * 4] = v;
        return;
    }

    __shared__ __align__(16) float As[2][32][68];
    __shared__ __align__(16) float Bs[2][32][68];

    const int g = b - 64;
    const int cx = g & 3, cy = g >> 2;
    const int c0 = cx * 64;
    const float* A = cy ? x2 : x1;          // 64 sample rows

    const int tx = tid & 15, ty = tid >> 4;
    const int lrow = tid >> 2, lk = (tid & 3) * 4;   // A-load: row, k-quad
    const int krow = tid >> 4, colq = tid & 15;      // B-load: k-row, col-quad

    float4 ra0, ra1, rb0, rb1;
    float acc[4][4] = {};

#define KA_LDG(kc) {                                                          \
    ra0 = *(const float4*)&A[lrow * D + (kc) + lk];                           \
    ra1 = *(const float4*)&A[lrow * D + (kc) + lk + 16];                      \
    rb0 = *(const float4*)&W1[((kc) + krow) * D + c0 + colq * 4];             \
    rb1 = *(const float4*)&W1[((kc) + krow + 16) * D + c0 + colq * 4];        \
}
#define KA_STS(buf) {                                                         \
    As[buf][lk + 0][lrow] = ra0.x; As[buf][lk + 1][lrow] = ra0.y;             \
    As[buf][lk + 2][lrow] = ra0.z; As[buf][lk + 3][lrow] = ra0.w;             \
    As[buf][lk + 16][lrow] = ra1.x; As[buf][lk + 17][lrow] = ra1.y;           \
    As[buf][lk + 18][lrow] = ra1.z; As[buf][lk + 19][lrow] = ra1.w;           \
    *(float4*)&Bs[buf][krow][colq * 4] = rb0;                                 \
    *(float4*)&Bs[buf][krow + 16][colq * 4] = rb1;                            \
}
#define KA_COMP(buf) {                                                        \
    _Pragma("unroll")                                                         \
    for (int k = 0; k < 32; k++) {                                            \
        float4 av = *(const float4*)&As[buf][k][ty * 4];                      \
        float4 bv = *(const float4*)&Bs[buf][k][tx * 4];                      \
        float a[4] = {av.x, av.y, av.z, av.w};                                \
        float bb[4] = {bv.x, bv.y, bv.z, bv.w};                               \
        _Pragma("unroll")                                                     \
        for (int i = 0; i < 4; i++)                                           \
            _Pragma("unroll")                                                 \
            for (int j = 0; j < 4; j++)                                       \
                acc[i][j] += a[i] * bb[j];                                    \
    } }

    KA_LDG(0); KA_STS(0); __syncthreads();
#pragma unroll 1
    for (int st = 0; st < 8; st++) {
        const int cur = st & 1;
        if (st < 7) KA_LDG((st + 1) * 32);
        KA_COMP(cur);
        if (st < 7) { KA_STS(cur ^ 1); __syncthreads(); }
    }
#undef KA_LDG
#undef KA_STS
#undef KA_COMP

    float4 bv = *(const float4*)&b1[c0 + tx * 4];
    float bb[4] = {bv.x, bv.y, bv.z, bv.w};
#pragma unroll
    for (int i = 0; i < 4; i++) {
        int s = cy * 64 + ty * 4 + i;
        float4 h;
        h.x = tanhf(acc[i][0] + bb[0]);
        h.y = tanhf(acc[i][1] + bb[1]);
        h.z = tanhf(acc[i][2] + bb[2]);
        h.w = tanhf(acc[i][3] + bb[3]);
        *(float4*)&d_H1[s * D + c0 + tx * 4] = h;
    }
}

// ======== kB: layer-2 GEMM  H2 = tanh(H1 @ W2 + b2), G2 = W3^T .* (1-H2^2) =======
__global__ __launch_bounds__(256) void kB_l2(
    const float* __restrict__ W2, const float* __restrict__ b2,
    const float* __restrict__ W3)
{
    __shared__ __align__(16) float As[2][32][68];
    __shared__ __align__(16) float Bs[2][32][68];
    __shared__ float sw3[64 * O];

    const int tid = threadIdx.x;
    const int g = blockIdx.x;
    const int cx = g & 3, cy = g >> 2;
    const int c0 = cx * 64;
    const float* A = d_H1 + cy * 64 * D;

    const int tx = tid & 15, ty = tid >> 4;
    const int lrow = tid >> 2, lk = (tid & 3) * 4;
    const int krow = tid >> 4, colq = tid & 15;

    // stage W3 block into smem: sw3[u*10+a] = W3[(c0+u)*10+a]
    for (int i = tid; i < 64 * O; i += 256) sw3[i] = W3[c0 * O + i];

    float4 ra0, ra1, rb0, rb1;
    float acc[4][4] = {};

#define KB_LDG(kc) {                                                          \
    ra0 = *(const float4*)&A[lrow * D + (kc) + lk];                           \
    ra1 = *(const float4*)&A[lrow * D + (kc) + lk + 16];                      \
    rb0 = *(const float4*)&W2[((kc) + krow) * D + c0 + colq * 4];             \
    rb1 = *(const float4*)&W2[((kc) + krow + 16) * D + c0 + colq * 4];        \
}
#define KB_STS(buf) {                                                         \
    As[buf][lk + 0][lrow] = ra0.x; As[buf][lk + 1][lrow] = ra0.y;             \
    As[buf][lk + 2][lrow] = ra0.z; As[buf][lk + 3][lrow] = ra0.w;             \
    As[buf][lk + 16][lrow] = ra1.x; As[buf][lk + 17][lrow] = ra1.y;           \
    As[buf][lk + 18][lrow] = ra1.z; As[buf][lk + 19][lrow] = ra1.w;           \
    *(float4*)&Bs[buf][krow][colq * 4] = rb0;                                 \
    *(float4*)&Bs[buf][krow + 16][colq * 4] = rb1;                            \
}
#define KB_COMP(buf) {                                                        \
    _Pragma("unroll")                                                         \
    for (int k = 0; k < 32; k++) {                                            \
        float4 av = *(const float4*)&As[buf][k][ty * 4];                      \
        float4 bv = *(const float4*)&Bs[buf][k][tx * 4];                      \
        float a[4] = {av.x, av.y, av.z, av.w};                                \
        float bb[4] = {bv.x, bv.y, bv.z, bv.w};                               \
        _Pragma("unroll")                                                     \
        for (int i = 0; i < 4; i++)                                           \
            _Pragma("unroll")                                                 \
            for (int j = 0; j < 4; j++)                                       \
                acc[i][j] += a[i] * bb[j];                                    \
    } }

    KB_LDG(0); KB_STS(0); __syncthreads();
#pragma unroll 1
    for (int st = 0; st < 8; st++) {
        const int cur = st & 1;
        if (st < 7) KB_LDG((st + 1) * 32);
        KB_COMP(cur);
        if (st < 7) { KB_STS(cur ^ 1); __syncthreads(); }
    }
#undef KB_LDG
#undef KB_STS
#undef KB_COMP

    float4 bv = *(const float4*)&b2[c0 + tx * 4];
    float bb[4] = {bv.x, bv.y, bv.z, bv.w};
    float w3l[4][O];
#pragma unroll
    for (int j = 0; j < 4; j++)
#pragma unroll
        for (int a = 0; a < O; a++)
            w3l[j][a] = sw3[(tx * 4 + j) * O + a];

#pragma unroll
    for (int i = 0; i < 4; i++) {
        int s = cy * 64 + ty * 4 + i;
        float h0 = tanhf(acc[i][0] + bb[0]);
        float h1 = tanhf(acc[i][1] + bb[1]);
        float h2 = tanhf(acc[i][2] + bb[2]);
        float h3 = tanhf(acc[i][3] + bb[3]);
        *(float4*)&d_H2[s * D + c0 + tx * 4] = make_float4(h0, h1, h2, h3);
        float t0 = 1.f - h0 * h0, t1 = 1.f - h1 * h1;
        float t2 = 1.f - h2 * h2, t3 = 1.f - h3 * h3;
#pragma unroll
        for (int a = 0; a < O; a++) {
            float4 gg = make_float4(w3l[0][a] * t0, w3l[1][a] * t1,
                                    w3l[2][a] * t2, w3l[3][a] * t3);
            *(float4*)&d_G2[(s * O + a) * D + c0 + tx * 4] = gg;
        }
    }
}

// ======== kC: G1 backward (blocks 0..255) + pairwise dots (256..319) ==============
__global__ __launch_bounds__(256) void kC_bwd_dots(
    const float* __restrict__ x1, const float* __restrict__ x2)
{
    __shared__ float sm[5 * D];
    const int b = blockIdx.x, t = threadIdx.x;

    if (b < 256) {
        const int s = b >> 1, half = b & 1;
#pragma unroll
        for (int j = 0; j < 5; j++)
            sm[j * D + t] = d_G2[(s * O + half * 5 + j) * D + t];
        float h1 = d_H1[s * D + t];
        float t1 = 1.0f - h1 * h1;
        __syncthreads();

        float a0 = 0.f, a1 = 0.f, a2 = 0.f, a3 = 0.f, a4 = 0.f;
#pragma unroll 4
        for (int k4 = 0; k4 < 64; k4++) {
            float4 w  = *(const float4*)&d_W2P[(k4 * D + t) * 4];
            float4 g0 = *(const float4*)&sm[0 * D + k4 * 4];
            float4 g1 = *(const float4*)&sm[1 * D + k4 * 4];
            float4 g2 = *(const float4*)&sm[2 * D + k4 * 4];
            float4 g3 = *(const float4*)&sm[3 * D + k4 * 4];
            float4 g4 = *(const float4*)&sm[4 * D + k4 * 4];
            a0 += w.x * g0.x + w.y * g0.y + w.z * g0.z + w.w * g0.w;
            a1 += w.x * g1.x + w.y * g1.y + w.z * g1.z + w.w * g1.w;
            a2 += w.x * g2.x + w.y * g2.y + w.z * g2.z + w.w * g2.w;
            a3 += w.x * g3.x + w.y * g3.y + w.z * g3.z + w.w * g3.w;
            a4 += w.x * g4.x + w.y * g4.y + w.z * g4.z + w.w * g4.w;
        }
        const int base = (s * O + half * 5) * D + t;
        d_G1[base + 0 * D] = t1 * a0;
        d_G1[base + 1 * D] = t1 * a1;
        d_G1[base + 2 * D] = t1 * a2;
        d_G1[base + 3 * D] = t1 * a3;
        d_G1[base + 4 * D] = t1 * a4;
        return;
    }

    const int n = b - 256;
    float* xa  = sm;
    float* h1a = sm + D;
    float* h2a = sm + 2 * D;
    xa[t]  = x1[n * D + t];
    h1a[t] = d_H1[n * D + t];
    h2a[t] = d_H2[n * D + t];
    __syncthreads();

    const int warp = t >> 5, lane = t & 31;
#pragma unroll
    for (int mi = 0; mi < 8; mi++) {
        int m = warp * 8 + mi;
        const float* x2r = x2 + m * D;
        const float* h1r = d_H1 + (NS + m) * D;
        const float* h2r = d_H2 + (NS + m) * D;
        float s0 = 0.f, s1 = 0.f, s2 = 0.f;
#pragma unroll
        for (int k = lane; k < D; k += 32) {
            s0 += xa[k]  * x2r[k];
            s1 += h1a[k] * h1r[k];
            s2 += h2a[k] * h2r[k];
        }
#pragma unroll
        for (int off = 16; off > 0; off >>= 1) {
            s0 += __shfl_down_sync(0xffffffffu, s0, off);
            s1 += __shfl_down_sync(0xffffffffu, s1, off);
            s2 += __shfl_down_sync(0xffffffffu, s2, off);
        }
        if (lane == 0) {
            d_C[0][n * NS + m] = s0 + 1.0f;
            d_C[1][n * NS + m] = s1 + 1.0f;
            d_C[2][n * NS + m] = s2 + 1.0f;
        }
    }
}

// ======== kD: fused pair-GEMMs (both layers, K=512) + NTK combine =================
// 64x64 tile, 256 threads, 4x4 micro x 2 layers, 32-deep double-buffered stages.
__global__ __launch_bounds__(256) void kD_pair(float* __restrict__ out)
{
    __shared__ __align__(16) float As[2][32][68];
    __shared__ __align__(16) float Bs[2][32][68];

    const int tid = threadIdx.x;
    const int tx = tid & 15, ty = tid >> 4;
    const int r0 = blockIdx.y * 64, c0 = blockIdx.x * 64;
    const int lrow = tid >> 2, lk = (tid & 3) * 4;

    float4 ra0, ra1, rb0, rb1;
    float acc0[4][4] = {};
    float acc1[4][4] = {};

#define KD_LDG(st) {                                                          \
    const float* G = ((st) < 8) ? d_G1 : d_G2;                                \
    const int kc = ((st) & 7) * 32;                                           \
    ra0 = *(const float4*)&G[(r0 + lrow) * D + kc + lk];                      \
    ra1 = *(const float4*)&G[(r0 + lrow) * D + kc + lk + 16];                 \
    rb0 = *(const float4*)&G[(R + c0 + lrow) * D + kc + lk];                  \
    rb1 = *(const float4*)&G[(R + c0 + lrow) * D + kc + lk + 16];             \
}
#define KD_STS(buf) {                                                         \
    As[buf][lk + 0][lrow] = ra0.x; As[buf][lk + 1][lrow] = ra0.y;             \
    As[buf][lk + 2][lrow] = ra0.z; As[buf][lk + 3][lrow] = ra0.w;             \
    As[buf][lk + 16][lrow] = ra1.x; As[buf][lk + 17][lrow] = ra1.y;           \
    As[buf][lk + 18][lrow] = ra1.z; As[buf][lk + 19][lrow] = ra1.w;           \
    Bs[buf][lk + 0][lrow] = rb0.x; Bs[buf][lk + 1][lrow] = rb0.y;             \
    Bs[buf][lk + 2][lrow] = rb0.z; Bs[buf][lk + 3][lrow] = rb0.w;             \
    Bs[buf][lk + 16][lrow] = rb1.x; Bs[buf][lk + 17][lrow] = rb1.y;           \
    Bs[buf][lk + 18][lrow] = rb1.z; Bs[buf][lk + 19][lrow] = rb1.w;           \
}
#define KD_COMP(buf, ACC) {                                                   \
    _Pragma("unroll")                                                         \
    for (int k = 0; k < 32; k++) {                                            \
        float4 av = *(const float4*)&As[buf][k][ty * 4];                      \
        float4 bv = *(const float4*)&Bs[buf][k][tx * 4];                      \
        float a[4] = {av.x, av.y, av.z, av.w};                                \
        float bb[4] = {bv.x, bv.y, bv.z, bv.w};                               \
        _Pragma("unroll")                                                     \
        for (int i = 0; i < 4; i++)                                           \
            _Pragma("unroll")                                                 \
            for (int j = 0; j < 4; j++)                                       \
                ACC[i][j] += a[i] * bb[j];                                    \
    } }

    KD_LDG(0); KD_STS(0); __syncthreads();
#pragma unroll 1
    for (int st = 0; st < 8; st++) {
        const int cur = st & 1;
        KD_LDG(st + 1);
        KD_COMP(cur, acc0);
        KD_STS(cur ^ 1);
        __syncthreads();
    }
#pragma unroll 1
    for (int st = 8; st < 16; st++) {
        const int cur = st & 1;
        if (st < 15) KD_LDG(st + 1);
        KD_COMP(cur, acc1);
        if (st < 15) { KD_STS(cur ^ 1); __syncthreads(); }
    }
#undef KD_LDG
#undef KD_STS
#undef KD_COMP

    // out[n,m,a,b] = C0*P0 + C1*P1 + (a==b)*C2
#pragma unroll
    for (int i = 0; i < 4; i++) {
        int row = r0 + ty * 4 + i;            // n*10 + a
        int n = row / 10, a = row - n * 10;
#pragma unroll
        for (int j = 0; j < 4; j++) {
            int col = c0 + tx * 4 + j;        // m*10 + b
            int m = col / 10, bb = col - m * 10;
            int ci = n * NS + m;
            float v = d_C[0][ci] * acc0[i][j] + d_C[1][ci] * acc1[i][j];
            if (a == bb) v += d_C[2][ci];
            out[(n * NS + m) * 100 + a * 10 + bb] = v;
        }
    }
}

// ---------------- launcher ----------------
extern "C" void kernel_launch(void* const* d_in, const int* in_sizes, int n_in,
                              void* d_out, int out_size) {
    const float* x1 = (const float*)d_in[0];
    const float* x2 = (const float*)d_in[1];
    const float* W1 = (const float*)d_in[2];
    const float* b1 = (const float*)d_in[3];
    const float* W2 = (const float*)d_in[4];
    const float* b2 = (const float*)d_in[5];
    const float* W3 = (const float*)d_in[6];
    float* out = (float*)d_out;

    kA_l1<<<72, 256>>>(x1, x2, W1, b1, W2);
    kB_l2<<<8, 256>>>(W2, b2, W3);
    kC_bwd_dots<<<320, 256>>>(x1, x2);
    kD_pair<<<dim3(10, 10), 256>>>(out);
}

// round 9
// speedup vs baseline: 1.1051x; 1.1051x over previous
#include <cuda_runtime.h>
#include <math.h>

#define D 256
#define O 10
#define NS 64
#define R 640   // NS*O

// ---------------- scratch ----------------
__device__ float d_W2P[D * D];     // float4 at (k4*D + t) holds W2[t][4k4..4k4+3]
__device__ float d_H1[2 * NS * D];
__device__ float d_H2[2 * NS * D];
__device__ float d_G1[2 * R * D];
__device__ float d_G2[2 * R * D];
__device__ float d_P[2][R * R];
__device__ float d_C[3][NS * NS];

// ---- shared forward-GEMM machinery: 32(samples) x 64(units), 256 thr, 2x4 micro,
//      K=256 in 8 double-buffered 32-deep stages ----
#define FWD_DECLS                                                              \
    __shared__ __align__(16) float As[2][32][36];                              \
    __shared__ __align__(16) float Bs[2][32][68];                              \
    const int tid = threadIdx.x;                                               \
    const int tx = tid & 15, ty = tid >> 4;                                    \
    const int arow = tid >> 3, akq = tid & 7;                                  \
    const int krow = tid >> 4, colq = tid & 15;                                \
    float4 ra, rb0, rb1;                                                       \
    float acc[2][4] = {};

#define FWD_LDG(Ap, Wp, kc) {                                                  \
    ra  = *(const float4*)&(Ap)[arow * D + (kc) + akq * 4];                    \
    rb0 = *(const float4*)&(Wp)[((kc) + krow) * D + c0 + colq * 4];            \
    rb1 = *(const float4*)&(Wp)[((kc) + krow + 16) * D + c0 + colq * 4];       \
}
#define FWD_STS(buf) {                                                         \
    As[buf][akq * 4 + 0][arow] = ra.x; As[buf][akq * 4 + 1][arow] = ra.y;      \
    As[buf][akq * 4 + 2][arow] = ra.z; As[buf][akq * 4 + 3][arow] = ra.w;      \
    *(float4*)&Bs[buf][krow][colq * 4] = rb0;                                  \
    *(float4*)&Bs[buf][krow + 16][colq * 4] = rb1;                             \
}
#define FWD_COMP(buf) {                                                        \
    _Pragma("unroll")                                                          \
    for (int k = 0; k < 32; k++) {                                             \
        float2 av = *(const float2*)&As[buf][k][ty * 2];                       \
        float4 bv = *(const float4*)&Bs[buf][k][tx * 4];                       \
        float a[2] = {av.x, av.y};                                             \
        float bb[4] = {bv.x, bv.y, bv.z, bv.w};                                \
        _Pragma("unroll")                                                      \
        for (int i = 0; i < 2; i++)                                            \
            _Pragma("unroll")                                                  \
            for (int j = 0; j < 4; j++)                                        \
                acc[i][j] += a[i] * bb[j];                                     \
    } }

#define FWD_LOOP(Ap, Wp)                                                       \
    FWD_LDG(Ap, Wp, 0); FWD_STS(0); __syncthreads();                           \
    _Pragma("unroll 1")                                                        \
    for (int st = 0; st < 8; st++) {                                           \
        const int cur = st & 1;                                                \
        if (st < 7) FWD_LDG(Ap, Wp, (st + 1) * 32);                            \
        FWD_COMP(cur);                                                         \
        if (st < 7) { FWD_STS(cur ^ 1); __syncthreads(); }                     \
    }

// ======== kA: H1 = tanh(X @ W1 + b1); blocks 0..63 = W2 pack, 64..79 = GEMM ======
__global__ __launch_bounds__(256) void kA_l1(
    const float* __restrict__ x1, const float* __restrict__ x2,
    const float* __restrict__ W1, const float* __restrict__ b1,
    const float* __restrict__ W2)
{
    const int b = blockIdx.x;

    if (b < 64) {
        int gid = b * 256 + threadIdx.x;
        int k4 = gid & 63, tw = gid >> 6;
        float4 v = *(const float4*)&W2[tw * D + k4 * 4];
        *(float4*)&d_W2P[(k4 * D + tw) * 4] = v;
        return;
    }

    const int g = b - 64;
    const int cx = g & 3, cy = g >> 2;         // cy: 0..3 (32-sample slabs)
    const int c0 = cx * 64;
    const float* A = (cy < 2) ? (x1 + cy * 32 * D) : (x2 + (cy - 2) * 32 * D);

    FWD_DECLS
    FWD_LOOP(A, W1)

    float4 bv = *(const float4*)&b1[c0 + tx * 4];
    float bb[4] = {bv.x, bv.y, bv.z, bv.w};
#pragma unroll
    for (int i = 0; i < 2; i++) {
        int s = cy * 32 + ty * 2 + i;
        float4 h;
        h.x = tanhf(acc[i][0] + bb[0]);
        h.y = tanhf(acc[i][1] + bb[1]);
        h.z = tanhf(acc[i][2] + bb[2]);
        h.w = tanhf(acc[i][3] + bb[3]);
        *(float4*)&d_H1[s * D + c0 + tx * 4] = h;
    }
}

// ======== kB: H2 = tanh(H1 @ W2 + b2), G2 = W3^T .* (1-H2^2) ======================
__global__ __launch_bounds__(256) void kB_l2(
    const float* __restrict__ W2, const float* __restrict__ b2,
    const float* __restrict__ W3)
{
    const int g = blockIdx.x;
    const int cx = g & 3, cy = g >> 2;
    const int c0 = cx * 64;
    const float* A = d_H1 + cy * 32 * D;

    __shared__ float sw3[64 * O];
    for (int i = threadIdx.x; i < 64 * O; i += 256) sw3[i] = W3[c0 * O + i];

    FWD_DECLS
    FWD_LOOP(A, W2)

    float4 bv = *(const float4*)&b2[c0 + tx * 4];
    float bb[4] = {bv.x, bv.y, bv.z, bv.w};
    float w3l[4][O];
#pragma unroll
    for (int j = 0; j < 4; j++)
#pragma unroll
        for (int a = 0; a < O; a++)
            w3l[j][a] = sw3[(tx * 4 + j) * O + a];

#pragma unroll
    for (int i = 0; i < 2; i++) {
        int s = cy * 32 + ty * 2 + i;
        float h0 = tanhf(acc[i][0] + bb[0]);
        float h1 = tanhf(acc[i][1] + bb[1]);
        float h2 = tanhf(acc[i][2] + bb[2]);
        float h3 = tanhf(acc[i][3] + bb[3]);
        *(float4*)&d_H2[s * D + c0 + tx * 4] = make_float4(h0, h1, h2, h3);
        float t0 = 1.f - h0 * h0, t1 = 1.f - h1 * h1;
        float t2 = 1.f - h2 * h2, t3 = 1.f - h3 * h3;
#pragma unroll
        for (int a = 0; a < O; a++) {
            float4 gg = make_float4(w3l[0][a] * t0, w3l[1][a] * t1,
                                    w3l[2][a] * t2, w3l[3][a] * t3);
            *(float4*)&d_G2[(s * O + a) * D + c0 + tx * 4] = gg;
        }
    }
}

// ======== kC: G1 backward (blocks 0..255) + pairwise dots (256..319) ==============
__global__ __launch_bounds__(256) void kC_bwd_dots(
    const float* __restrict__ x1, const float* __restrict__ x2)
{
    __shared__ float sm[5 * D];
    const int b = blockIdx.x, t = threadIdx.x;

    if (b < 256) {
        const int s = b >> 1, half = b & 1;
#pragma unroll
        for (int j = 0; j < 5; j++)
            sm[j * D + t] = d_G2[(s * O + half * 5 + j) * D + t];
        float h1 = d_H1[s * D + t];
        float t1 = 1.0f - h1 * h1;
        __syncthreads();

        float a0 = 0.f, a1 = 0.f, a2 = 0.f, a3 = 0.f, a4 = 0.f;
#pragma unroll 4
        for (int k4 = 0; k4 < 64; k4++) {
            float4 w  = *(const float4*)&d_W2P[(k4 * D + t) * 4];
            float4 g0 = *(const float4*)&sm[0 * D + k4 * 4];
            float4 g1 = *(const float4*)&sm[1 * D + k4 * 4];
            float4 g2 = *(const float4*)&sm[2 * D + k4 * 4];
            float4 g3 = *(const float4*)&sm[3 * D + k4 * 4];
            float4 g4 = *(const float4*)&sm[4 * D + k4 * 4];
            a0 += w.x * g0.x + w.y * g0.y + w.z * g0.z + w.w * g0.w;
            a1 += w.x * g1.x + w.y * g1.y + w.z * g1.z + w.w * g1.w;
            a2 += w.x * g2.x + w.y * g2.y + w.z * g2.z + w.w * g2.w;
            a3 += w.x * g3.x + w.y * g3.y + w.z * g3.z + w.w * g3.w;
            a4 += w.x * g4.x + w.y * g4.y + w.z * g4.z + w.w * g4.w;
        }
        const int base = (s * O + half * 5) * D + t;
        d_G1[base + 0 * D] = t1 * a0;
        d_G1[base + 1 * D] = t1 * a1;
        d_G1[base + 2 * D] = t1 * a2;
        d_G1[base + 3 * D] = t1 * a3;
        d_G1[base + 4 * D] = t1 * a4;
        return;
    }

    const int n = b - 256;
    float* xa  = sm;
    float* h1a = sm + D;
    float* h2a = sm + 2 * D;
    xa[t]  = x1[n * D + t];
    h1a[t] = d_H1[n * D + t];
    h2a[t] = d_H2[n * D + t];
    __syncthreads();

    const int warp = t >> 5, lane = t & 31;
#pragma unroll
    for (int mi = 0; mi < 8; mi++) {
        int m = warp * 8 + mi;
        const float* x2r = x2 + m * D;
        const float* h1r = d_H1 + (NS + m) * D;
        const float* h2r = d_H2 + (NS + m) * D;
        float s0 = 0.f, s1 = 0.f, s2 = 0.f;
#pragma unroll
        for (int k = lane; k < D; k += 32) {
            s0 += xa[k]  * x2r[k];
            s1 += h1a[k] * h1r[k];
            s2 += h2a[k] * h2r[k];
        }
#pragma unroll
        for (int off = 16; off > 0; off >>= 1) {
            s0 += __shfl_down_sync(0xffffffffu, s0, off);
            s1 += __shfl_down_sync(0xffffffffu, s1, off);
            s2 += __shfl_down_sync(0xffffffffu, s2, off);
        }
        if (lane == 0) {
            d_C[0][n * NS + m] = s0 + 1.0f;
            d_C[1][n * NS + m] = s1 + 1.0f;
            d_C[2][n * NS + m] = s2 + 1.0f;
        }
    }
}

// ======== gemm64: P_l = G_l1[640,256] @ G_l2[640,256]^T (double-buffered, R7) =====
__global__ __launch_bounds__(256) void gemm64() {
    const int layer = blockIdx.z;
    const float* G = (layer == 0) ? d_G1 : d_G2;
    const float* A = G;
    const float* B = G + R * D;
    float* P = d_P[layer];

    __shared__ __align__(16) float As[2][16][68];
    __shared__ __align__(16) float Bs[2][16][68];

    const int tid = threadIdx.x;
    const int tx = tid & 15, ty = tid >> 4;
    const int r0 = blockIdx.y * 64, c0 = blockIdx.x * 64;
    const int lrow = tid >> 2;
    const int lk   = (tid & 3) * 4;

    float4 a4, b4;
    float acc[4][4] = {};

#define G64_LDG(kc) {                                                         \
    a4 = *(const float4*)&A[(r0 + lrow) * D + (kc) + lk];                     \
    b4 = *(const float4*)&B[(c0 + lrow) * D + (kc) + lk];                     \
}
#define G64_STS(buf) {                                                        \
    As[buf][lk + 0][lrow] = a4.x; As[buf][lk + 1][lrow] = a4.y;               \
    As[buf][lk + 2][lrow] = a4.z; As[buf][lk + 3][lrow] = a4.w;               \
    Bs[buf][lk + 0][lrow] = b4.x; Bs[buf][lk + 1][lrow] = b4.y;               \
    Bs[buf][lk + 2][lrow] = b4.z; Bs[buf][lk + 3][lrow] = b4.w;               \
}

    G64_LDG(0); G64_STS(0); __syncthreads();

#pragma unroll 1
    for (int st = 0; st < 16; st++) {
        const int cur = st & 1;
        if (st < 15) G64_LDG((st + 1) * 16);
#pragma unroll
        for (int k = 0; k < 16; k++) {
            float4 av = *(const float4*)&As[cur][k][ty * 4];
            float4 bv = *(const float4*)&Bs[cur][k][tx * 4];
            float a[4] = {av.x, av.y, av.z, av.w};
            float bb[4] = {bv.x, bv.y, bv.z, bv.w};
#pragma unroll
            for (int i = 0; i < 4; i++)
#pragma unroll
                for (int j = 0; j < 4; j++)
                    acc[i][j] += a[i] * bb[j];
        }
        if (st < 15) { G64_STS(cur ^ 1); __syncthreads(); }
    }
#undef G64_LDG
#undef G64_STS

#pragma unroll
    for (int i = 0; i < 4; i++) {
        float4 v = make_float4(acc[i][0], acc[i][1], acc[i][2], acc[i][3]);
        *(float4*)&P[(r0 + ty * 4 + i) * R + c0 + tx * 4] = v;
    }
}

// ======== combine =================================================================
__global__ __launch_bounds__(256) void combine_kernel(float* __restrict__ out) {
    int idx = blockIdx.x * 256 + threadIdx.x;
    if (idx >= NS * NS * O * O) return;
    int n  = idx / (NS * O * O);
    int r  = idx % (NS * O * O);
    int m  = r / (O * O);
    int ab = r % (O * O);
    int a = ab / O, b = ab % O;
    int pidx = (n * O + a) * R + (m * O + b);
    int cidx = n * NS + m;
    float v = d_C[0][cidx] * d_P[0][pidx]
            + d_C[1][cidx] * d_P[1][pidx];
    if (a == b) v += d_C[2][cidx];
    out[idx] = v;
}

// ---------------- launcher ----------------
extern "C" void kernel_launch(void* const* d_in, const int* in_sizes, int n_in,
                              void* d_out, int out_size) {
    const float* x1 = (const float*)d_in[0];
    const float* x2 = (const float*)d_in[1];
    const float* W1 = (const float*)d_in[2];
    const float* b1 = (const float*)d_in[3];
    const float* W2 = (const float*)d_in[4];
    const float* b2 = (const float*)d_in[5];
    const float* W3 = (const float*)d_in[6];
    float* out = (float*)d_out;

    kA_l1<<<80, 256>>>(x1, x2, W1, b1, W2);
    kB_l2<<<16, 256>>>(W2, b2, W3);
    kC_bwd_dots<<<320, 256>>>(x1, x2);
    gemm64<<<dim3(10, 10, 2), 256>>>();
    combine_kernel<<<(NS * NS * O * O + 255) / 256, 256>>>(out);
}

// round 10
// speedup vs baseline: 1.1894x; 1.0762x over previous
#include <cuda_runtime.h>
#include <math.h>
#include <stdint.h>

#define D 256
#define O 10
#define NS 64
#define R 640   // NS*O

// ---------------- scratch ----------------
__device__ float d_W2P[D * D];     // float4 at (k4*D + t) holds W2[t][4k4..4k4+3]
__device__ float d_H1[2 * NS * D];
__device__ float d_H2[2 * NS * D];
__device__ float d_G1[2 * R * D];
__device__ float d_G2[2 * R * D];
__device__ float d_C[3][NS * NS];

// ---------------- tf32 helpers ----------------
__device__ __forceinline__ uint32_t f2tf32(float f) {
    uint32_t r;
    asm("cvt.rna.tf32.f32 %0, %1;" : "=r"(r) : "f"(f));
    return r;
}
__device__ __forceinline__ void mma_tf32(
    float& c0, float& c1, float& c2, float& c3,
    uint32_t a0, uint32_t a1, uint32_t a2, uint32_t a3,
    uint32_t b0, uint32_t b1)
{
    asm volatile(
        "mma.sync.aligned.m16n8k8.row.col.f32.tf32.tf32.f32 "
        "{%0,%1,%2,%3}, {%4,%5,%6,%7}, {%8,%9}, {%0,%1,%2,%3};"
        : "+f"(c0), "+f"(c1), "+f"(c2), "+f"(c3)
        : "r"(a0), "r"(a1), "r"(a2), "r"(a3), "r"(b0), "r"(b1));
}

// ---- shared forward-GEMM machinery (R9, measured): 32x64, 256 thr, 2x4 micro ----
#define FWD_DECLS                                                              \
    __shared__ __align__(16) float As[2][32][36];                              \
    __shared__ __align__(16) float Bs[2][32][68];                              \
    const int tid = threadIdx.x;                                               \
    const int tx = tid & 15, ty = tid >> 4;                                    \
    const int arow = tid >> 3, akq = tid & 7;                                  \
    const int krow = tid >> 4, colq = tid & 15;                                \
    float4 ra, rb0, rb1;                                                       \
    float acc[2][4] = {};

#define FWD_LDG(Ap, Wp, kc) {                                                  \
    ra  = *(const float4*)&(Ap)[arow * D + (kc) + akq * 4];                    \
    rb0 = *(const float4*)&(Wp)[((kc) + krow) * D + c0 + colq * 4];            \
    rb1 = *(const float4*)&(Wp)[((kc) + krow + 16) * D + c0 + colq * 4];       \
}
#define FWD_STS(buf) {                                                         \
    As[buf][akq * 4 + 0][arow] = ra.x; As[buf][akq * 4 + 1][arow] = ra.y;      \
    As[buf][akq * 4 + 2][arow] = ra.z; As[buf][akq * 4 + 3][arow] = ra.w;      \
    *(float4*)&Bs[buf][krow][colq * 4] = rb0;                                  \
    *(float4*)&Bs[buf][krow + 16][colq * 4] = rb1;                             \
}
#define FWD_COMP(buf) {                                                        \
    _Pragma("unroll")                                                          \
    for (int k = 0; k < 32; k++) {                                             \
        float2 av = *(const float2*)&As[buf][k][ty * 2];                       \
        float4 bv = *(const float4*)&Bs[buf][k][tx * 4];                       \
        float a[2] = {av.x, av.y};                                             \
        float bb[4] = {bv.x, bv.y, bv.z, bv.w};                                \
        _Pragma("unroll")                                                      \
        for (int i = 0; i < 2; i++)                                            \
            _Pragma("unroll")                                                  \
            for (int j = 0; j < 4; j++)                                        \
                acc[i][j] += a[i] * bb[j];                                     \
    } }

#define FWD_LOOP(Ap, Wp)                                                       \
    FWD_LDG(Ap, Wp, 0); FWD_STS(0); __syncthreads();                           \
    _Pragma("unroll 1")                                                        \
    for (int st = 0; st < 8; st++) {                                           \
        const int cur = st & 1;                                                \
        if (st < 7) FWD_LDG(Ap, Wp, (st + 1) * 32);                            \
        FWD_COMP(cur);                                                         \
        if (st < 7) { FWD_STS(cur ^ 1); __syncthreads(); }                     \
    }

// ======== kA: H1 = tanh(X @ W1 + b1); blocks 0..63 = W2 pack, 64..79 = GEMM ======
__global__ __launch_bounds__(256) void kA_l1(
    const float* __restrict__ x1, const float* __restrict__ x2,
    const float* __restrict__ W1, const float* __restrict__ b1,
    const float* __restrict__ W2)
{
    const int b = blockIdx.x;

    if (b < 64) {
        int gid = b * 256 + threadIdx.x;
        int k4 = gid & 63, tw = gid >> 6;
        float4 v = *(const float4*)&W2[tw * D + k4 * 4];
        *(float4*)&d_W2P[(k4 * D + tw) * 4] = v;
        return;
    }

    const int g = b - 64;
    const int cx = g & 3, cy = g >> 2;
    const int c0 = cx * 64;
    const float* A = (cy < 2) ? (x1 + cy * 32 * D) : (x2 + (cy - 2) * 32 * D);

    FWD_DECLS
    FWD_LOOP(A, W1)

    float4 bv = *(const float4*)&b1[c0 + tx * 4];
    float bb[4] = {bv.x, bv.y, bv.z, bv.w};
#pragma unroll
    for (int i = 0; i < 2; i++) {
        int s = cy * 32 + ty * 2 + i;
        float4 h;
        h.x = tanhf(acc[i][0] + bb[0]);
        h.y = tanhf(acc[i][1] + bb[1]);
        h.z = tanhf(acc[i][2] + bb[2]);
        h.w = tanhf(acc[i][3] + bb[3]);
        *(float4*)&d_H1[s * D + c0 + tx * 4] = h;
    }
}

// ======== kB: H2 = tanh(H1 @ W2 + b2), G2 = W3^T .* (1-H2^2) ======================
__global__ __launch_bounds__(256) void kB_l2(
    const float* __restrict__ W2, const float* __restrict__ b2,
    const float* __restrict__ W3)
{
    const int g = blockIdx.x;
    const int cx = g & 3, cy = g >> 2;
    const int c0 = cx * 64;
    const float* A = d_H1 + cy * 32 * D;

    __shared__ float sw3[64 * O];
    for (int i = threadIdx.x; i < 64 * O; i += 256) sw3[i] = W3[c0 * O + i];

    FWD_DECLS
    FWD_LOOP(A, W2)

    float4 bv = *(const float4*)&b2[c0 + tx * 4];
    float bb[4] = {bv.x, bv.y, bv.z, bv.w};
    float w3l[4][O];
#pragma unroll
    for (int j = 0; j < 4; j++)
#pragma unroll
        for (int a = 0; a < O; a++)
            w3l[j][a] = sw3[(tx * 4 + j) * O + a];

#pragma unroll
    for (int i = 0; i < 2; i++) {
        int s = cy * 32 + ty * 2 + i;
        float h0 = tanhf(acc[i][0] + bb[0]);
        float h1 = tanhf(acc[i][1] + bb[1]);
        float h2 = tanhf(acc[i][2] + bb[2]);
        float h3 = tanhf(acc[i][3] + bb[3]);
        *(float4*)&d_H2[s * D + c0 + tx * 4] = make_float4(h0, h1, h2, h3);
        float t0 = 1.f - h0 * h0, t1 = 1.f - h1 * h1;
        float t2 = 1.f - h2 * h2, t3 = 1.f - h3 * h3;
#pragma unroll
        for (int a = 0; a < O; a++) {
            float4 gg = make_float4(w3l[0][a] * t0, w3l[1][a] * t1,
                                    w3l[2][a] * t2, w3l[3][a] * t3);
            *(float4*)&d_G2[(s * O + a) * D + c0 + tx * 4] = gg;
        }
    }
}

// ======== kC: G1 backward (blocks 0..255) + pairwise dots (256..319) ==============
__global__ __launch_bounds__(256) void kC_bwd_dots(
    const float* __restrict__ x1, const float* __restrict__ x2)
{
    __shared__ float sm[5 * D];
    const int b = blockIdx.x, t = threadIdx.x;

    if (b < 256) {
        const int s = b >> 1, half = b & 1;
#pragma unroll
        for (int j = 0; j < 5; j++)
            sm[j * D + t] = d_G2[(s * O + half * 5 + j) * D + t];
        float h1 = d_H1[s * D + t];
        float t1 = 1.0f - h1 * h1;
        __syncthreads();

        float a0 = 0.f, a1 = 0.f, a2 = 0.f, a3 = 0.f, a4 = 0.f;
#pragma unroll 4
        for (int k4 = 0; k4 < 64; k4++) {
            float4 w  = *(const float4*)&d_W2P[(k4 * D + t) * 4];
            float4 g0 = *(const float4*)&sm[0 * D + k4 * 4];
            float4 g1 = *(const float4*)&sm[1 * D + k4 * 4];
            float4 g2 = *(const float4*)&sm[2 * D + k4 * 4];
            float4 g3 = *(const float4*)&sm[3 * D + k4 * 4];
            float4 g4 = *(const float4*)&sm[4 * D + k4 * 4];
            a0 += w.x * g0.x + w.y * g0.y + w.z * g0.z + w.w * g0.w;
            a1 += w.x * g1.x + w.y * g1.y + w.z * g1.z + w.w * g1.w;
            a2 += w.x * g2.x + w.y * g2.y + w.z * g2.z + w.w * g2.w;
            a3 += w.x * g3.x + w.y * g3.y + w.z * g3.z + w.w * g3.w;
            a4 += w.x * g4.x + w.y * g4.y + w.z * g4.z + w.w * g4.w;
        }
        const int base = (s * O + half * 5) * D + t;
        d_G1[base + 0 * D] = t1 * a0;
        d_G1[base + 1 * D] = t1 * a1;
        d_G1[base + 2 * D] = t1 * a2;
        d_G1[base + 3 * D] = t1 * a3;
        d_G1[base + 4 * D] = t1 * a4;
        return;
    }

    const int n = b - 256;
    float* xa  = sm;
    float* h1a = sm + D;
    float* h2a = sm + 2 * D;
    xa[t]  = x1[n * D + t];
    h1a[t] = d_H1[n * D + t];
    h2a[t] = d_H2[n * D + t];
    __syncthreads();

    const int warp = t >> 5, lane = t & 31;
#pragma unroll
    for (int mi = 0; mi < 8; mi++) {
        int m = warp * 8 + mi;
        const float* x2r = x2 + m * D;
        const float* h1r = d_H1 + (NS + m) * D;
        const float* h2r = d_H2 + (NS + m) * D;
        float s0 = 0.f, s1 = 0.f, s2 = 0.f;
#pragma unroll
        for (int k = lane; k < D; k += 32) {
            s0 += xa[k]  * x2r[k];
            s1 += h1a[k] * h1r[k];
            s2 += h2a[k] * h2r[k];
        }
#pragma unroll
        for (int off = 16; off > 0; off >>= 1) {
            s0 += __shfl_down_sync(0xffffffffu, s0, off);
            s1 += __shfl_down_sync(0xffffffffu, s1, off);
            s2 += __shfl_down_sync(0xffffffffu, s2, off);
        }
        if (lane == 0) {
            d_C[0][n * NS + m] = s0 + 1.0f;
            d_C[1][n * NS + m] = s1 + 1.0f;
            d_C[2][n * NS + m] = s2 + 1.0f;
        }
    }
}

// ======== kP: tensor-core pair-GEMMs (3xTF32, both layers) + fused NTK combine ====
// 64x64 tile, 256 thr (8 warps). warp w: row-tile rt=w&3 (16 rows), col-half
// ch=w>>2 (32 cols = 4 n-tiles of 8). K=256 per layer in 8 stages of 32.
// P = Ahi*Bhi + Ahi*Blo + Alo*Bhi  (fp32-grade accuracy).
__global__ __launch_bounds__(256) void kP_pair(float* __restrict__ out)
{
    __shared__ float sAhi[64][36];
    __shared__ float sAlo[64][36];
    __shared__ float sBhi[64][36];
    __shared__ float sBlo[64][36];

    const int tid  = threadIdx.x;
    const int lane = tid & 31;
    const int w    = tid >> 5;
    const int g    = lane >> 2;      // group 0..7
    const int t4   = lane & 3;       // 0..3
    const int rt   = w & 3;          // row-tile
    const int ch   = w >> 2;         // col half
    const int r0 = blockIdx.y * 64, c0 = blockIdx.x * 64;

    float acc[2][4][4];
#pragma unroll
    for (int l = 0; l < 2; l++)
#pragma unroll
        for (int nt = 0; nt < 4; nt++)
#pragma unroll
            for (int q = 0; q < 4; q++) acc[l][nt][q] = 0.f;

#pragma unroll
    for (int layer = 0; layer < 2; layer++) {
        const float* G = (layer == 0) ? d_G1 : d_G2;
        const float* GA = G + r0 * D;
        const float* GB = G + (R + c0) * D;

#pragma unroll 1
        for (int st = 0; st < 8; st++) {
            const int kc = st * 32;
            __syncthreads();   // previous stage fully consumed
            // stage: load 64x32 of A and B, split hi/lo, store row-major
#pragma unroll
            for (int p = 0; p < 2; p++) {
                int s = tid + p * 256;
                int row = s >> 3, q = (s & 7) * 4;
                float4 va = *(const float4*)&GA[row * D + kc + q];
                float4 vb = *(const float4*)&GB[row * D + kc + q];
                float av[4] = {va.x, va.y, va.z, va.w};
                float bv[4] = {vb.x, vb.y, vb.z, vb.w};
                float ah[4], al[4], bh[4], bl[4];
#pragma unroll
                for (int j = 0; j < 4; j++) {
                    uint32_t h = f2tf32(av[j]);
                    ah[j] = __uint_as_float(h);
                    al[j] = __uint_as_float(f2tf32(av[j] - ah[j]));
                    h = f2tf32(bv[j]);
                    bh[j] = __uint_as_float(h);
                    bl[j] = __uint_as_float(f2tf32(bv[j] - bh[j]));
                }
                *(float4*)&sAhi[row][q] = make_float4(ah[0], ah[1], ah[2], ah[3]);
                *(float4*)&sAlo[row][q] = make_float4(al[0], al[1], al[2], al[3]);
                *(float4*)&sBhi[row][q] = make_float4(bh[0], bh[1], bh[2], bh[3]);
                *(float4*)&sBlo[row][q] = make_float4(bl[0], bl[1], bl[2], bl[3]);
            }
            __syncthreads();

            // MMA over this 32-k stage: 4 k-chunks of 8
#pragma unroll
            for (int kk = 0; kk < 4; kk++) {
                const int kb = kk * 8 + t4;
                const int ar = rt * 16 + g;
                uint32_t ah0 = __float_as_uint(sAhi[ar][kb]);
                uint32_t ah1 = __float_as_uint(sAhi[ar + 8][kb]);
                uint32_t ah2 = __float_as_uint(sAhi[ar][kb + 4]);
                uint32_t ah3 = __float_as_uint(sAhi[ar + 8][kb + 4]);
                uint32_t al0 = __float_as_uint(sAlo[ar][kb]);
                uint32_t al1 = __float_as_uint(sAlo[ar + 8][kb]);
                uint32_t al2 = __float_as_uint(sAlo[ar][kb + 4]);
                uint32_t al3 = __float_as_uint(sAlo[ar + 8][kb + 4]);
#pragma unroll
                for (int nt = 0; nt < 4; nt++) {
                    const int nb = ch * 32 + nt * 8 + g;
                    uint32_t bh0 = __float_as_uint(sBhi[nb][kb]);
                    uint32_t bh1 = __float_as_uint(sBhi[nb][kb + 4]);
                    uint32_t bl0 = __float_as_uint(sBlo[nb][kb]);
                    uint32_t bl1 = __float_as_uint(sBlo[nb][kb + 4]);
                    float* c = acc[layer][nt];
                    mma_tf32(c[0], c[1], c[2], c[3], ah0, ah1, ah2, ah3, bh0, bh1);
                    mma_tf32(c[0], c[1], c[2], c[3], ah0, ah1, ah2, ah3, bl0, bl1);
                    mma_tf32(c[0], c[1], c[2], c[3], al0, al1, al2, al3, bh0, bh1);
                }
            }
        }
    }

    // ---- epilogue: out[n,m,a,b] = C0*P0 + C1*P1 + (a==b)*C2 ----
    const float* C0 = d_C[0];
    const float* C1 = d_C[1];
    const float* C2 = d_C[2];
#pragma unroll
    for (int nt = 0; nt < 4; nt++) {
        int col = c0 + ch * 32 + nt * 8 + 2 * t4;
        int m0 = col / 10,       bb0 = col - m0 * 10;
        int m1 = (col + 1) / 10, bb1 = (col + 1) - m1 * 10;
#pragma unroll
        for (int half = 0; half < 2; half++) {
            int row = r0 + rt * 16 + g + half * 8;
            int n = row / 10, a = row - n * 10;
            int ci0 = n * NS + m0, ci1 = n * NS + m1;
            float v0 = C0[ci0] * acc[0][nt][half * 2 + 0]
                     + C1[ci0] * acc[1][nt][half * 2 + 0];
            float v1 = C0[ci1] * acc[0][nt][half * 2 + 1]
                     + C1[ci1] * acc[1][nt][half * 2 + 1];
            if (a == bb0) v0 += C2[ci0];
            if (a == bb1) v1 += C2[ci1];
            out[ci0 * 100 + a * 10 + bb0] = v0;
            out[ci1 * 100 + a * 10 + bb1] = v1;
        }
    }
}

// ---------------- launcher ----------------
extern "C" void kernel_launch(void* const* d_in, const int* in_sizes, int n_in,
                              void* d_out, int out_size) {
    const float* x1 = (const float*)d_in[0];
    const float* x2 = (const float*)d_in[1];
    const float* W1 = (const float*)d_in[2];
    const float* b1 = (const float*)d_in[3];
    const float* W2 = (const float*)d_in[4];
    const float* b2 = (const float*)d_in[5];
    const float* W3 = (const float*)d_in[6];
    float* out = (float*)d_out;

    kA_l1<<<80, 256>>>(x1, x2, W1, b1, W2);
    kB_l2<<<16, 256>>>(W2, b2, W3);
    kC_bwd_dots<<<320, 256>>>(x1, x2);
    kP_pair<<<dim3(10, 10), 256>>>(out);
}

// round 11
// speedup vs baseline: 1.2876x; 1.0825x over previous
#include <cuda_runtime.h>
#include <math.h>
#include <stdint.h>

#define D 256
#define O 10
#define NS 64
#define R 640   // NS*O

// ---------------- scratch ----------------
__device__ float d_W2P[D * D];     // float4 at (k4*D + t) holds W2[t][4k4..4k4+3]
__device__ float d_H1[2 * NS * D];
__device__ float d_H2[2 * NS * D];
__device__ float d_G1[2 * R * D];
__device__ float d_G2[2 * R * D];
__device__ float d_C[3][NS * NS];

// ---------------- tf32 helpers ----------------
__device__ __forceinline__ uint32_t f2tf32(float f) {
    uint32_t r;
    asm("cvt.rna.tf32.f32 %0, %1;" : "=r"(r) : "f"(f));
    return r;
}
__device__ __forceinline__ void mma_tf32(
    float& c0, float& c1, float& c2, float& c3,
    uint32_t a0, uint32_t a1, uint32_t a2, uint32_t a3,
    uint32_t b0, uint32_t b1)
{
    asm volatile(
        "mma.sync.aligned.m16n8k8.row.col.f32.tf32.tf32.f32 "
        "{%0,%1,%2,%3}, {%4,%5,%6,%7}, {%8,%9}, {%0,%1,%2,%3};"
        : "+f"(c0), "+f"(c1), "+f"(c2), "+f"(c3)
        : "r"(a0), "r"(a1), "r"(a2), "r"(a3), "r"(b0), "r"(b1));
}

// ================= K1: W2 pack (blocks 0..63) + fused forward, 2 samples/CTA =====
// (R7 version — measured-best forward)
__global__ __launch_bounds__(256) void k1_fwd(
    const float* __restrict__ x1, const float* __restrict__ x2,
    const float* __restrict__ W1, const float* __restrict__ b1,
    const float* __restrict__ W2, const float* __restrict__ b2,
    const float* __restrict__ W3)
{
    __shared__ __align__(8) float2 xT[D];
    __shared__ __align__(8) float2 h1T[D];

    const int b = blockIdx.x, t = threadIdx.x;

    if (b < 64) {
        int gid = b * 256 + t;
        int k4 = gid & 63, tw = gid >> 6;
        float4 v = *(const float4*)&W2[tw * D + k4 * 4];
        *(float4*)&d_W2P[(k4 * D + tw) * 4] = v;
        return;
    }

    const int s0 = (b - 64) * 2;
    const float* xr0 = (s0 < NS) ? (x1 + s0 * D) : (x2 + (s0 - NS) * D);
    const float* xr1 = (s0 + 1 < NS) ? (x1 + (s0 + 1) * D) : (x2 + (s0 + 1 - NS) * D);
    xT[t] = make_float2(xr0[t], xr1[t]);
    __syncthreads();

    float bias = b1[t];
    float a0 = bias, a1 = 0.f;
    float c0 = bias, c1 = 0.f;
#pragma unroll 16
    for (int i = 0; i < D; i += 2) {
        float w0 = W1[i * D + t];
        float w1 = W1[(i + 1) * D + t];
        float2 x0 = xT[i];
        float2 x1v = xT[i + 1];
        a0 += x0.x * w0;  c0 += x0.y * w0;
        a1 += x1v.x * w1; c1 += x1v.y * w1;
    }
    float h1_0 = tanhf(a0 + a1), h1_1 = tanhf(c0 + c1);
    d_H1[(s0 + 0) * D + t] = h1_0;
    d_H1[(s0 + 1) * D + t] = h1_1;
    h1T[t] = make_float2(h1_0, h1_1);
    __syncthreads();

    bias = b2[t];
    a0 = bias; a1 = 0.f; c0 = bias; c1 = 0.f;
#pragma unroll 16
    for (int i = 0; i < D; i += 2) {
        float w0 = W2[i * D + t];
        float w1 = W2[(i + 1) * D + t];
        float2 h0 = h1T[i];
        float2 h1v = h1T[i + 1];
        a0 += h0.x * w0;  c0 += h0.y * w0;
        a1 += h1v.x * w1; c1 += h1v.y * w1;
    }
    float h2_0 = tanhf(a0 + a1), h2_1 = tanhf(c0 + c1);
    d_H2[(s0 + 0) * D + t] = h2_0;
    d_H2[(s0 + 1) * D + t] = h2_1;
    float t20 = 1.f - h2_0 * h2_0, t21 = 1.f - h2_1 * h2_1;

#pragma unroll
    for (int a = 0; a < O; a++) {
        float w3 = W3[t * O + a];
        d_G2[((s0 + 0) * O + a) * D + t] = w3 * t20;
        d_G2[((s0 + 1) * O + a) * D + t] = w3 * t21;
    }
}

// ======== kC: G1 backward (blocks 0..255) + pairwise dots (256..319) ==============
__global__ __launch_bounds__(256) void kC_bwd_dots(
    const float* __restrict__ x1, const float* __restrict__ x2)
{
    __shared__ float sm[5 * D];
    const int b = blockIdx.x, t = threadIdx.x;

    if (b < 256) {
        const int s = b >> 1, half = b & 1;
#pragma unroll
        for (int j = 0; j < 5; j++)
            sm[j * D + t] = d_G2[(s * O + half * 5 + j) * D + t];
        float h1 = d_H1[s * D + t];
        float t1 = 1.0f - h1 * h1;
        __syncthreads();

        float a0 = 0.f, a1 = 0.f, a2 = 0.f, a3 = 0.f, a4 = 0.f;
#pragma unroll 4
        for (int k4 = 0; k4 < 64; k4++) {
            float4 w  = *(const float4*)&d_W2P[(k4 * D + t) * 4];
            float4 g0 = *(const float4*)&sm[0 * D + k4 * 4];
            float4 g1 = *(const float4*)&sm[1 * D + k4 * 4];
            float4 g2 = *(const float4*)&sm[2 * D + k4 * 4];
            float4 g3 = *(const float4*)&sm[3 * D + k4 * 4];
            float4 g4 = *(const float4*)&sm[4 * D + k4 * 4];
            a0 += w.x * g0.x + w.y * g0.y + w.z * g0.z + w.w * g0.w;
            a1 += w.x * g1.x + w.y * g1.y + w.z * g1.z + w.w * g1.w;
            a2 += w.x * g2.x + w.y * g2.y + w.z * g2.z + w.w * g2.w;
            a3 += w.x * g3.x + w.y * g3.y + w.z * g3.z + w.w * g3.w;
            a4 += w.x * g4.x + w.y * g4.y + w.z * g4.z + w.w * g4.w;
        }
        const int base = (s * O + half * 5) * D + t;
        d_G1[base + 0 * D] = t1 * a0;
        d_G1[base + 1 * D] = t1 * a1;
        d_G1[base + 2 * D] = t1 * a2;
        d_G1[base + 3 * D] = t1 * a3;
        d_G1[base + 4 * D] = t1 * a4;
        return;
    }

    const int n = b - 256;
    float* xa  = sm;
    float* h1a = sm + D;
    float* h2a = sm + 2 * D;
    xa[t]  = x1[n * D + t];
    h1a[t] = d_H1[n * D + t];
    h2a[t] = d_H2[n * D + t];
    __syncthreads();

    const int warp = t >> 5, lane = t & 31;
#pragma unroll
    for (int mi = 0; mi < 8; mi++) {
        int m = warp * 8 + mi;
        const float* x2r = x2 + m * D;
        const float* h1r = d_H1 + (NS + m) * D;
        const float* h2r = d_H2 + (NS + m) * D;
        float s0 = 0.f, s1 = 0.f, s2 = 0.f;
#pragma unroll
        for (int k = lane; k < D; k += 32) {
            s0 += xa[k]  * x2r[k];
            s1 += h1a[k] * h1r[k];
            s2 += h2a[k] * h2r[k];
        }
#pragma unroll
        for (int off = 16; off > 0; off >>= 1) {
            s0 += __shfl_down_sync(0xffffffffu, s0, off);
            s1 += __shfl_down_sync(0xffffffffu, s1, off);
            s2 += __shfl_down_sync(0xffffffffu, s2, off);
        }
        if (lane == 0) {
            d_C[0][n * NS + m] = s0 + 1.0f;
            d_C[1][n * NS + m] = s1 + 1.0f;
            d_C[2][n * NS + m] = s2 + 1.0f;
        }
    }
}

// ======== kP: tensor-core pair-GEMMs (3xTF32, both layers) + fused NTK combine ====
// 64x64 tile, 256 thr (8 warps). warp w: row-tile rt=w&3 (16 rows), col-half
// ch=w>>2 (32 cols = 4 n-tiles of 8). K=256 per layer in 8 stages of 32.
// Dual accumulator chains per nt: c_hh (Ahi*Bhi) and c_cr (Ahi*Blo + Alo*Bhi).
__global__ __launch_bounds__(256) void kP_pair(float* __restrict__ out)
{
    __shared__ float sAhi[64][36];
    __shared__ float sAlo[64][36];
    __shared__ float sBhi[64][36];
    __shared__ float sBlo[64][36];

    const int tid  = threadIdx.x;
    const int lane = tid & 31;
    const int w    = tid >> 5;
    const int g    = lane >> 2;
    const int t4   = lane & 3;
    const int rt   = w & 3;
    const int ch   = w >> 2;
    const int r0 = blockIdx.y * 64, c0 = blockIdx.x * 64;

    float acc_h[2][4][4];
    float acc_c[2][4][4];
#pragma unroll
    for (int l = 0; l < 2; l++)
#pragma unroll
        for (int nt = 0; nt < 4; nt++)
#pragma unroll
            for (int q = 0; q < 4; q++) { acc_h[l][nt][q] = 0.f; acc_c[l][nt][q] = 0.f; }

#pragma unroll
    for (int layer = 0; layer < 2; layer++) {
        const float* G = (layer == 0) ? d_G1 : d_G2;
        const float* GA = G + r0 * D;
        const float* GB = G + (R + c0) * D;

#pragma unroll 1
        for (int st = 0; st < 8; st++) {
            const int kc = st * 32;
            __syncthreads();
#pragma unroll
            for (int p = 0; p < 2; p++) {
                int s = tid + p * 256;
                int row = s >> 3, q = (s & 7) * 4;
                float4 va = *(const float4*)&GA[row * D + kc + q];
                float4 vb = *(const float4*)&GB[row * D + kc + q];
                float av[4] = {va.x, va.y, va.z, va.w};
                float bv[4] = {vb.x, vb.y, vb.z, vb.w};
                float ah[4], al[4], bh[4], bl[4];
#pragma unroll
                for (int j = 0; j < 4; j++) {
                    uint32_t h = f2tf32(av[j]);
                    ah[j] = __uint_as_float(h);
                    al[j] = __uint_as_float(f2tf32(av[j] - ah[j]));
                    h = f2tf32(bv[j]);
                    bh[j] = __uint_as_float(h);
                    bl[j] = __uint_as_float(f2tf32(bv[j] - bh[j]));
                }
                *(float4*)&sAhi[row][q] = make_float4(ah[0], ah[1], ah[2], ah[3]);
                *(float4*)&sAlo[row][q] = make_float4(al[0], al[1], al[2], al[3]);
                *(float4*)&sBhi[row][q] = make_float4(bh[0], bh[1], bh[2], bh[3]);
                *(float4*)&sBlo[row][q] = make_float4(bl[0], bl[1], bl[2], bl[3]);
            }
            __syncthreads();

#pragma unroll
            for (int kk = 0; kk < 4; kk++) {
                const int kb = kk * 8 + t4;
                const int ar = rt * 16 + g;
                uint32_t ah0 = __float_as_uint(sAhi[ar][kb]);
                uint32_t ah1 = __float_as_uint(sAhi[ar + 8][kb]);
                uint32_t ah2 = __float_as_uint(sAhi[ar][kb + 4]);
                uint32_t ah3 = __float_as_uint(sAhi[ar + 8][kb + 4]);
                uint32_t al0 = __float_as_uint(sAlo[ar][kb]);
                uint32_t al1 = __float_as_uint(sAlo[ar + 8][kb]);
                uint32_t al2 = __float_as_uint(sAlo[ar][kb + 4]);
                uint32_t al3 = __float_as_uint(sAlo[ar + 8][kb + 4]);
#pragma unroll
                for (int nt = 0; nt < 4; nt++) {
                    const int nb = ch * 32 + nt * 8 + g;
                    uint32_t bh0 = __float_as_uint(sBhi[nb][kb]);
                    uint32_t bh1 = __float_as_uint(sBhi[nb][kb + 4]);
                    uint32_t bl0 = __float_as_uint(sBlo[nb][kb]);
                    uint32_t bl1 = __float_as_uint(sBlo[nb][kb + 4]);
                    float* chh = acc_h[layer][nt];
                    float* ccr = acc_c[layer][nt];
                    mma_tf32(chh[0], chh[1], chh[2], chh[3], ah0, ah1, ah2, ah3, bh0, bh1);
                    mma_tf32(ccr[0], ccr[1], ccr[2], ccr[3], ah0, ah1, ah2, ah3, bl0, bl1);
                    mma_tf32(ccr[0], ccr[1], ccr[2], ccr[3], al0, al1, al2, al3, bh0, bh1);
                }
            }
        }
    }

    // ---- epilogue: out[n,m,a,b] = C0*P0 + C1*P1 + (a==b)*C2 ----
    const float* C0 = d_C[0];
    const float* C1 = d_C[1];
    const float* C2 = d_C[2];
#pragma unroll
    for (int nt = 0; nt < 4; nt++) {
        int col = c0 + ch * 32 + nt * 8 + 2 * t4;
        int m0 = col / 10,       bb0 = col - m0 * 10;
        int m1 = (col + 1) / 10, bb1 = (col + 1) - m1 * 10;
#pragma unroll
        for (int half = 0; half < 2; half++) {
            int row = r0 + rt * 16 + g + half * 8;
            int n = row / 10, a = row - n * 10;
            int ci0 = n * NS + m0, ci1 = n * NS + m1;
            float p00 = acc_h[0][nt][half * 2 + 0] + acc_c[0][nt][half * 2 + 0];
            float p10 = acc_h[1][nt][half * 2 + 0] + acc_c[1][nt][half * 2 + 0];
            float p01 = acc_h[0][nt][half * 2 + 1] + acc_c[0][nt][half * 2 + 1];
            float p11 = acc_h[1][nt][half * 2 + 1] + acc_c[1][nt][half * 2 + 1];
            float v0 = C0[ci0] * p00 + C1[ci0] * p10;
            float v1 = C0[ci1] * p01 + C1[ci1] * p11;
            if (a == bb0) v0 += C2[ci0];
            if (a == bb1) v1 += C2[ci1];
            out[ci0 * 100 + a * 10 + bb0] = v0;
            out[ci1 * 100 + a * 10 + bb1] = v1;
        }
    }
}

// ---------------- launcher ----------------
extern "C" void kernel_launch(void* const* d_in, const int* in_sizes, int n_in,
                              void* d_out, int out_size) {
    const float* x1 = (const float*)d_in[0];
    const float* x2 = (const float*)d_in[1];
    const float* W1 = (const float*)d_in[2];
    const float* b1 = (const float*)d_in[3];
    const float* W2 = (const float*)d_in[4];
    const float* b2 = (const float*)d_in[5];
    const float* W3 = (const float*)d_in[6];
    float* out = (float*)d_out;

    k1_fwd<<<128, 256>>>(x1, x2, W1, b1, W2, b2, W3);
    kC_bwd_dots<<<320, 256>>>(x1, x2);
    kP_pair<<<dim3(10, 10), 256>>>(out);
}

// round 12
// speedup vs baseline: 1.3955x; 1.0839x over previous
#include <cuda_runtime.h>
#include <math.h>
#include <stdint.h>

#define D 256
#define O 10
#define NS 64
#define R 640   // NS*O

// ---------------- scratch ----------------
__device__ float d_W2P[D * D];     // float4 at (k4*D + t) holds W2[t][4k4..4k4+3]
__device__ float d_H1[2 * NS * D];
__device__ float d_H2[2 * NS * D];
__device__ float d_G1[2 * R * D];
__device__ float d_G2[2 * R * D];
__device__ float d_C[3][NS * NS];

// ---------------- tf32 helpers ----------------
__device__ __forceinline__ uint32_t f2tf32(float f) {
    uint32_t r;
    asm("cvt.rna.tf32.f32 %0, %1;" : "=r"(r) : "f"(f));
    return r;
}
__device__ __forceinline__ void mma_tf32(
    float& c0, float& c1, float& c2, float& c3,
    uint32_t a0, uint32_t a1, uint32_t a2, uint32_t a3,
    uint32_t b0, uint32_t b1)
{
    asm volatile(
        "mma.sync.aligned.m16n8k8.row.col.f32.tf32.tf32.f32 "
        "{%0,%1,%2,%3}, {%4,%5,%6,%7}, {%8,%9}, {%0,%1,%2,%3};"
        : "+f"(c0), "+f"(c1), "+f"(c2), "+f"(c3)
        : "r"(a0), "r"(a1), "r"(a2), "r"(a3), "r"(b0), "r"(b1));
}

// ================= K1: W2 pack (blocks 0..63) + fused forward, 2 samples/CTA =====
// Register-double-buffered 16-wide W load batches; launch_bounds(256,1) lifts the
// 32-reg cap so 16 LDGs stay in flight while the other buffer's FMAs run.
__global__ __launch_bounds__(256, 1) void k1_fwd(
    const float* __restrict__ x1, const float* __restrict__ x2,
    const float* __restrict__ W1, const float* __restrict__ b1,
    const float* __restrict__ W2, const float* __restrict__ b2,
    const float* __restrict__ W3)
{
    __shared__ __align__(8) float2 xT[D];
    __shared__ __align__(8) float2 h1T[D];

    const int b = blockIdx.x, t = threadIdx.x;

    if (b < 64) {
        int gid = b * 256 + t;
        int k4 = gid & 63, tw = gid >> 6;
        float4 v = *(const float4*)&W2[tw * D + k4 * 4];
        *(float4*)&d_W2P[(k4 * D + tw) * 4] = v;
        return;
    }

    const int s0 = (b - 64) * 2;
    const float* xr0 = (s0 < NS) ? (x1 + s0 * D) : (x2 + (s0 - NS) * D);
    const float* xr1 = (s0 + 1 < NS) ? (x1 + (s0 + 1) * D) : (x2 + (s0 + 1 - NS) * D);
    xT[t] = make_float2(xr0[t], xr1[t]);
    __syncthreads();

    float w0[16], w1[16];

#define K1_LAYER(Wp, SRC, A0, A1, C0, C1)                                      \
    _Pragma("unroll")                                                          \
    for (int j = 0; j < 16; j++) w0[j] = (Wp)[j * D + t];                      \
    _Pragma("unroll 1")                                                        \
    for (int ib = 0; ib < D; ib += 32) {                                       \
        _Pragma("unroll")                                                      \
        for (int j = 0; j < 16; j++) w1[j] = (Wp)[(ib + 16 + j) * D + t];      \
        _Pragma("unroll")                                                      \
        for (int j = 0; j < 16; j += 2) {                                      \
            float2 xa = SRC[ib + j], xb = SRC[ib + j + 1];                     \
            A0 += xa.x * w0[j];     C0 += xa.y * w0[j];                        \
            A1 += xb.x * w0[j + 1]; C1 += xb.y * w0[j + 1];                    \
        }                                                                      \
        if (ib + 32 < D) {                                                     \
            _Pragma("unroll")                                                  \
            for (int j = 0; j < 16; j++) w0[j] = (Wp)[(ib + 32 + j) * D + t];  \
        }                                                                      \
        _Pragma("unroll")                                                      \
        for (int j = 0; j < 16; j += 2) {                                      \
            float2 xa = SRC[ib + 16 + j], xb = SRC[ib + 16 + j + 1];           \
            A0 += xa.x * w1[j];     C0 += xa.y * w1[j];                        \
            A1 += xb.x * w1[j + 1]; C1 += xb.y * w1[j + 1];                    \
        }                                                                      \
    }

    // ---- layer 1 ----
    float bias = b1[t];
    float a0 = bias, a1 = 0.f, c0 = bias, c1 = 0.f;
    K1_LAYER(W1, xT, a0, a1, c0, c1)
    float h1_0 = tanhf(a0 + a1), h1_1 = tanhf(c0 + c1);
    d_H1[(s0 + 0) * D + t] = h1_0;
    d_H1[(s0 + 1) * D + t] = h1_1;
    h1T[t] = make_float2(h1_0, h1_1);
    __syncthreads();

    // ---- layer 2 ----
    bias = b2[t];
    a0 = bias; a1 = 0.f; c0 = bias; c1 = 0.f;
    K1_LAYER(W2, h1T, a0, a1, c0, c1)
    float h2_0 = tanhf(a0 + a1), h2_1 = tanhf(c0 + c1);
    d_H2[(s0 + 0) * D + t] = h2_0;
    d_H2[(s0 + 1) * D + t] = h2_1;
    float t20 = 1.f - h2_0 * h2_0, t21 = 1.f - h2_1 * h2_1;

#pragma unroll
    for (int a = 0; a < O; a++) {
        float w3 = W3[t * O + a];
        d_G2[((s0 + 0) * O + a) * D + t] = w3 * t20;
        d_G2[((s0 + 1) * O + a) * D + t] = w3 * t21;
    }
#undef K1_LAYER
}

// ======== kC: G1 backward (blocks 0..255) + pairwise dots (256..319) ==============
__global__ __launch_bounds__(256) void kC_bwd_dots(
    const float* __restrict__ x1, const float* __restrict__ x2)
{
    __shared__ float sm[5 * D];
    const int b = blockIdx.x, t = threadIdx.x;

    if (b < 256) {
        const int s = b >> 1, half = b & 1;
#pragma unroll
        for (int j = 0; j < 5; j++)
            sm[j * D + t] = d_G2[(s * O + half * 5 + j) * D + t];
        float h1 = d_H1[s * D + t];
        float t1 = 1.0f - h1 * h1;
        __syncthreads();

        float a0 = 0.f, a1 = 0.f, a2 = 0.f, a3 = 0.f, a4 = 0.f;
#pragma unroll 4
        for (int k4 = 0; k4 < 64; k4++) {
            float4 w  = *(const float4*)&d_W2P[(k4 * D + t) * 4];
            float4 g0 = *(const float4*)&sm[0 * D + k4 * 4];
            float4 g1 = *(const float4*)&sm[1 * D + k4 * 4];
            float4 g2 = *(const float4*)&sm[2 * D + k4 * 4];
            float4 g3 = *(const float4*)&sm[3 * D + k4 * 4];
            float4 g4 = *(const float4*)&sm[4 * D + k4 * 4];
            a0 += w.x * g0.x + w.y * g0.y + w.z * g0.z + w.w * g0.w;
            a1 += w.x * g1.x + w.y * g1.y + w.z * g1.z + w.w * g1.w;
            a2 += w.x * g2.x + w.y * g2.y + w.z * g2.z + w.w * g2.w;
            a3 += w.x * g3.x + w.y * g3.y + w.z * g3.z + w.w * g3.w;
            a4 += w.x * g4.x + w.y * g4.y + w.z * g4.z + w.w * g4.w;
        }
        const int base = (s * O + half * 5) * D + t;
        d_G1[base + 0 * D] = t1 * a0;
        d_G1[base + 1 * D] = t1 * a1;
        d_G1[base + 2 * D] = t1 * a2;
        d_G1[base + 3 * D] = t1 * a3;
        d_G1[base + 4 * D] = t1 * a4;
        return;
    }

    const int n = b - 256;
    float* xa  = sm;
    float* h1a = sm + D;
    float* h2a = sm + 2 * D;
    xa[t]  = x1[n * D + t];
    h1a[t] = d_H1[n * D + t];
    h2a[t] = d_H2[n * D + t];
    __syncthreads();

    const int warp = t >> 5, lane = t & 31;
#pragma unroll
    for (int mi = 0; mi < 8; mi++) {
        int m = warp * 8 + mi;
        const float* x2r = x2 + m * D;
        const float* h1r = d_H1 + (NS + m) * D;
        const float* h2r = d_H2 + (NS + m) * D;
        float s0 = 0.f, s1 = 0.f, s2 = 0.f;
#pragma unroll
        for (int k = lane; k < D; k += 32) {
            s0 += xa[k]  * x2r[k];
            s1 += h1a[k] * h1r[k];
            s2 += h2a[k] * h2r[k];
        }
#pragma unroll
        for (int off = 16; off > 0; off >>= 1) {
            s0 += __shfl_down_sync(0xffffffffu, s0, off);
            s1 += __shfl_down_sync(0xffffffffu, s1, off);
            s2 += __shfl_down_sync(0xffffffffu, s2, off);
        }
        if (lane == 0) {
            d_C[0][n * NS + m] = s0 + 1.0f;
            d_C[1][n * NS + m] = s1 + 1.0f;
            d_C[2][n * NS + m] = s2 + 1.0f;
        }
    }
}

// ======== kP: tensor-core pair-GEMMs (3xTF32, both layers) + fused NTK combine ====
// 64x64 tile, 512 thr (16 warps): warp w -> row-tile rt=w&3 (16 rows),
// col-quarter cq=w>>2 (16 cols = 2 n-tiles). Dual acc chains (hh / cross).
__global__ __launch_bounds__(512) void kP_pair(float* __restrict__ out)
{
    __shared__ float sAhi[64][36];
    __shared__ float sAlo[64][36];
    __shared__ float sBhi[64][36];
    __shared__ float sBlo[64][36];

    const int tid  = threadIdx.x;
    const int lane = tid & 31;
    const int w    = tid >> 5;      // 0..15
    const int g    = lane >> 2;
    const int t4   = lane & 3;
    const int rt   = w & 3;
    const int cq   = w >> 2;        // 0..3
    const int r0 = blockIdx.y * 64, c0 = blockIdx.x * 64;

    float acc_h[2][2][4];
    float acc_c[2][2][4];
#pragma unroll
    for (int l = 0; l < 2; l++)
#pragma unroll
        for (int nt = 0; nt < 2; nt++)
#pragma unroll
            for (int q = 0; q < 4; q++) { acc_h[l][nt][q] = 0.f; acc_c[l][nt][q] = 0.f; }

    const int srow = tid >> 3;           // 0..63
    const int sq   = (tid & 7) * 4;      // 0..28

#pragma unroll
    for (int layer = 0; layer < 2; layer++) {
        const float* G = (layer == 0) ? d_G1 : d_G2;
        const float* GA = G + r0 * D;
        const float* GB = G + (R + c0) * D;

#pragma unroll 1
        for (int st = 0; st < 8; st++) {
            const int kc = st * 32;
            __syncthreads();
            {
                float4 va = *(const float4*)&GA[srow * D + kc + sq];
                float4 vb = *(const float4*)&GB[srow * D + kc + sq];
                float av[4] = {va.x, va.y, va.z, va.w};
                float bv[4] = {vb.x, vb.y, vb.z, vb.w};
                float ah[4], al[4], bh[4], bl[4];
#pragma unroll
                for (int j = 0; j < 4; j++) {
                    uint32_t h = f2tf32(av[j]);
                    ah[j] = __uint_as_float(h);
                    al[j] = __uint_as_float(f2tf32(av[j] - ah[j]));
                    h = f2tf32(bv[j]);
                    bh[j] = __uint_as_float(h);
                    bl[j] = __uint_as_float(f2tf32(bv[j] - bh[j]));
                }
                *(float4*)&sAhi[srow][sq] = make_float4(ah[0], ah[1], ah[2], ah[3]);
                *(float4*)&sAlo[srow][sq] = make_float4(al[0], al[1], al[2], al[3]);
                *(float4*)&sBhi[srow][sq] = make_float4(bh[0], bh[1], bh[2], bh[3]);
                *(float4*)&sBlo[srow][sq] = make_float4(bl[0], bl[1], bl[2], bl[3]);
            }
            __syncthreads();

#pragma unroll
            for (int kk = 0; kk < 4; kk++) {
                const int kb = kk * 8 + t4;
                const int ar = rt * 16 + g;
                uint32_t ah0 = __float_as_uint(sAhi[ar][kb]);
                uint32_t ah1 = __float_as_uint(sAhi[ar + 8][kb]);
                uint32_t ah2 = __float_as_uint(sAhi[ar][kb + 4]);
                uint32_t ah3 = __float_as_uint(sAhi[ar + 8][kb + 4]);
                uint32_t al0 = __float_as_uint(sAlo[ar][kb]);
                uint32_t al1 = __float_as_uint(sAlo[ar + 8][kb]);
                uint32_t al2 = __float_as_uint(sAlo[ar][kb + 4]);
                uint32_t al3 = __float_as_uint(sAlo[ar + 8][kb + 4]);
#pragma unroll
                for (int nt = 0; nt < 2; nt++) {
                    const int nb = cq * 16 + nt * 8 + g;
                    uint32_t bh0 = __float_as_uint(sBhi[nb][kb]);
                    uint32_t bh1 = __float_as_uint(sBhi[nb][kb + 4]);
                    uint32_t bl0 = __float_as_uint(sBlo[nb][kb]);
                    uint32_t bl1 = __float_as_uint(sBlo[nb][kb + 4]);
                    float* chh = acc_h[layer][nt];
                    float* ccr = acc_c[layer][nt];
                    mma_tf32(chh[0], chh[1], chh[2], chh[3], ah0, ah1, ah2, ah3, bh0, bh1);
                    mma_tf32(ccr[0], ccr[1], ccr[2], ccr[3], ah0, ah1, ah2, ah3, bl0, bl1);
                    mma_tf32(ccr[0], ccr[1], ccr[2], ccr[3], al0, al1, al2, al3, bh0, bh1);
                }
            }
        }
    }

    // ---- epilogue: out[n,m,a,b] = C0*P0 + C1*P1 + (a==b)*C2 ----
    const float* C0 = d_C[0];
    const float* C1 = d_C[1];
    const float* C2 = d_C[2];
#pragma unroll
    for (int nt = 0; nt < 2; nt++) {
        int col = c0 + cq * 16 + nt * 8 + 2 * t4;
        int m0 = col / 10,       bb0 = col - m0 * 10;
        int m1 = (col + 1) / 10, bb1 = (col + 1) - m1 * 10;
#pragma unroll
        for (int half = 0; half < 2; half++) {
            int row = r0 + rt * 16 + g + half * 8;
            int n = row / 10, a = row - n * 10;
            int ci0 = n * NS + m0, ci1 = n * NS + m1;
            float p00 = acc_h[0][nt][half * 2 + 0] + acc_c[0][nt][half * 2 + 0];
            float p10 = acc_h[1][nt][half * 2 + 0] + acc_c[1][nt][half * 2 + 0];
            float p01 = acc_h[0][nt][half * 2 + 1] + acc_c[0][nt][half * 2 + 1];
            float p11 = acc_h[1][nt][half * 2 + 1] + acc_c[1][nt][half * 2 + 1];
            float v0 = C0[ci0] * p00 + C1[ci0] * p10;
            float v1 = C0[ci1] * p01 + C1[ci1] * p11;
            if (a == bb0) v0 += C2[ci0];
            if (a == bb1) v1 += C2[ci1];
            out[ci0 * 100 + a * 10 + bb0] = v0;
            out[ci1 * 100 + a * 10 + bb1] = v1;
        }
    }
}

// ---------------- launcher ----------------
extern "C" void kernel_launch(void* const* d_in, const int* in_sizes, int n_in,
                              void* d_out, int out_size) {
    const float* x1 = (const float*)d_in[0];
    const float* x2 = (const float*)d_in[1];
    const float* W1 = (const float*)d_in[2];
    const float* b1 = (const float*)d_in[3];
    const float* W2 = (const float*)d_in[4];
    const float* b2 = (const float*)d_in[5];
    const float* W3 = (const float*)d_in[6];
    float* out = (float*)d_out;

    k1_fwd<<<128, 256>>>(x1, x2, W1, b1, W2, b2, W3);
    kC_bwd_dots<<<320, 256>>>(x1, x2);
    kP_pair<<<dim3(10, 10), 512>>>(out);
}